// round 10
// baseline (speedup 1.0000x reference)
#include <cuda_runtime.h>

// Problem constants
#define BSZ   16
#define MOUT  128
#define CBLK  8
#define NCH   1024
#define TLEN  2048
#define T4    (TLEN / 4)   // 512 float4 per row

// 128-bit read-only global load with 256B L2 fetch granularity.
// Sequential-stream friendly: halves LTS request count per byte.
static __device__ __forceinline__ float4 ldg_nc_256(const float4* p) {
    float4 v;
    asm volatile("ld.global.nc.L2::256B.v4.f32 {%0,%1,%2,%3}, [%4];"
                 : "=f"(v.x), "=f"(v.y), "=f"(v.z), "=f"(v.w)
                 : "l"(p));
    return v;
}

// Fused kernel, flattened & barrier-free (R6 structure), 256B L2 fetches:
//  Ax[b,m,t] = sum_c x[b, m*8+c, t] * tanh(blocks[m,c])
//  One CTA of 512 threads per (b,m) row; each thread produces one float4.
//  The 8 loads issue FIRST; tanh weights are computed per-warp (lanes 0-7)
//  and shuffle-broadcast while the loads are in flight — no __syncthreads,
//  no shared memory.
//  CTAs with b==0 additionally write A_full row m (first 256 threads).
__global__ void __launch_bounds__(512, 4)
fused_kernel(const float* __restrict__ x,
             const float* __restrict__ blocks,
             float* __restrict__ ax_out,
             float* __restrict__ afull_out)
{
    const int bm   = blockIdx.x;          // 0 .. BSZ*MOUT-1
    const int m    = bm & (MOUT - 1);
    const int b    = bm >> 7;             // bm / MOUT
    const int lane = threadIdx.x & 31;
    const int t    = threadIdx.x;         // 0 .. 511 — one float4 per thread

    const float4* __restrict__ xb =
        reinterpret_cast<const float4*>(x + ((size_t)b * NCH + (size_t)m * CBLK) * TLEN);
    float4* __restrict__ ob =
        reinterpret_cast<float4*>(ax_out + ((size_t)b * MOUT + m) * TLEN);

    // ---- Issue all 8 loads first (read-only path, 256B L2 granularity) ----
    float4 v0 = ldg_nc_256(xb + 0 * T4 + t);
    float4 v1 = ldg_nc_256(xb + 1 * T4 + t);
    float4 v2 = ldg_nc_256(xb + 2 * T4 + t);
    float4 v3 = ldg_nc_256(xb + 3 * T4 + t);
    float4 v4 = ldg_nc_256(xb + 4 * T4 + t);
    float4 v5 = ldg_nc_256(xb + 5 * T4 + t);
    float4 v6 = ldg_nc_256(xb + 6 * T4 + t);
    float4 v7 = ldg_nc_256(xb + 7 * T4 + t);

    // ---- Compute weights under the load shadow: lane-parallel tanh + shfl ----
    const float wv = tanhf(__ldg(blocks + m * CBLK + (lane & 7)));
    const float w0 = __shfl_sync(0xffffffffu, wv, 0);
    const float w1 = __shfl_sync(0xffffffffu, wv, 1);
    const float w2 = __shfl_sync(0xffffffffu, wv, 2);
    const float w3 = __shfl_sync(0xffffffffu, wv, 3);
    const float w4 = __shfl_sync(0xffffffffu, wv, 4);
    const float w5 = __shfl_sync(0xffffffffu, wv, 5);
    const float w6 = __shfl_sync(0xffffffffu, wv, 6);
    const float w7 = __shfl_sync(0xffffffffu, wv, 7);

    float4 acc;
    acc.x = v0.x * w0;  acc.y = v0.y * w0;  acc.z = v0.z * w0;  acc.w = v0.w * w0;
    acc.x += v1.x * w1; acc.y += v1.y * w1; acc.z += v1.z * w1; acc.w += v1.w * w1;
    acc.x += v2.x * w2; acc.y += v2.y * w2; acc.z += v2.z * w2; acc.w += v2.w * w2;
    acc.x += v3.x * w3; acc.y += v3.y * w3; acc.z += v3.z * w3; acc.w += v3.w * w3;
    acc.x += v4.x * w4; acc.y += v4.y * w4; acc.z += v4.z * w4; acc.w += v4.w * w4;
    acc.x += v5.x * w5; acc.y += v5.y * w5; acc.z += v5.z * w5; acc.w += v5.w * w5;
    acc.x += v6.x * w6; acc.y += v6.y * w6; acc.z += v6.z * w6; acc.w += v6.w * w6;
    acc.x += v7.x * w7; acc.y += v7.y * w7; acc.z += v7.z * w7; acc.w += v7.w * w7;
    ob[t] = acc;   // default write-back store — L2-absorbed (R9: policy-neutral)

    // A_full[m, j] = (j>>3 == m) ? tanh(blocks[j]) : 0 — b==0 CTAs, 256 float4/row.
    if (b == 0 && threadIdx.x < 256) {
        const int j0 = threadIdx.x * 4;
        float4 a = make_float4(0.f, 0.f, 0.f, 0.f);
        if ((j0 >> 3) == m) {
            if (j0 & 4) { a.x = w4; a.y = w5; a.z = w6; a.w = w7; }
            else        { a.x = w0; a.y = w1; a.z = w2; a.w = w3; }
        }
        reinterpret_cast<float4*>(afull_out + (size_t)m * NCH)[threadIdx.x] = a;
    }
}

extern "C" void kernel_launch(void* const* d_in, const int* in_sizes, int n_in,
                              void* d_out, int out_size)
{
    const float* x      = (const float*)d_in[0];
    const float* blocks = (const float*)d_in[1];
    float* out = (float*)d_out;

    // Output layout: Ax (B*M*T floats) followed by A_full (M*NCH floats)
    float* ax_out    = out;
    float* afull_out = out + (size_t)BSZ * MOUT * TLEN;

    fused_kernel<<<BSZ * MOUT, 512>>>(x, blocks, ax_out, afull_out);
}

// round 11
// speedup vs baseline: 1.0588x; 1.0588x over previous
#include <cuda_runtime.h>

// Problem constants
#define BSZ   16
#define MOUT  128
#define CBLK  8
#define NCH   1024
#define TLEN  2048
#define T4    (TLEN / 4)   // 512 float4 per row

// 128-bit streaming global load (evict-first) with 256B L2 fetch granularity.
// .cs keeps the R9-proven no-L1-allocate policy; L2::256B halves LTS request
// count per byte on a perfectly sequential stream.
static __device__ __forceinline__ float4 ldg_cs_256(const float4* p) {
    float4 v;
    asm volatile("ld.global.cs.L2::256B.v4.f32 {%0,%1,%2,%3}, [%4];"
                 : "=f"(v.x), "=f"(v.y), "=f"(v.z), "=f"(v.w)
                 : "l"(p));
    return v;
}

// Fused kernel, flattened & barrier-free (R9 structure), cs+256B loads:
//  Ax[b,m,t] = sum_c x[b, m*8+c, t] * tanh(blocks[m,c])
//  One CTA of 512 threads per (b,m) row; each thread produces one float4.
//  The 8 loads issue FIRST; tanh weights are computed per-warp (lanes 0-7)
//  and shuffle-broadcast while the loads are in flight — no __syncthreads,
//  no shared memory. Stores: default write-back (R9: policy-neutral).
//  CTAs with b==0 additionally write A_full row m (first 256 threads).
__global__ void __launch_bounds__(512, 4)
fused_kernel(const float* __restrict__ x,
             const float* __restrict__ blocks,
             float* __restrict__ ax_out,
             float* __restrict__ afull_out)
{
    const int bm   = blockIdx.x;          // 0 .. BSZ*MOUT-1
    const int m    = bm & (MOUT - 1);
    const int b    = bm >> 7;             // bm / MOUT
    const int lane = threadIdx.x & 31;
    const int t    = threadIdx.x;         // 0 .. 511 — one float4 per thread

    const float4* __restrict__ xb =
        reinterpret_cast<const float4*>(x + ((size_t)b * NCH + (size_t)m * CBLK) * TLEN);
    float4* __restrict__ ob =
        reinterpret_cast<float4*>(ax_out + ((size_t)b * MOUT + m) * TLEN);

    // ---- Issue all 8 streaming loads first (evict-first, 256B L2 fetch) ----
    float4 v0 = ldg_cs_256(xb + 0 * T4 + t);
    float4 v1 = ldg_cs_256(xb + 1 * T4 + t);
    float4 v2 = ldg_cs_256(xb + 2 * T4 + t);
    float4 v3 = ldg_cs_256(xb + 3 * T4 + t);
    float4 v4 = ldg_cs_256(xb + 4 * T4 + t);
    float4 v5 = ldg_cs_256(xb + 5 * T4 + t);
    float4 v6 = ldg_cs_256(xb + 6 * T4 + t);
    float4 v7 = ldg_cs_256(xb + 7 * T4 + t);

    // ---- Compute weights under the load shadow: lane-parallel tanh + shfl ----
    const float wv = tanhf(__ldg(blocks + m * CBLK + (lane & 7)));
    const float w0 = __shfl_sync(0xffffffffu, wv, 0);
    const float w1 = __shfl_sync(0xffffffffu, wv, 1);
    const float w2 = __shfl_sync(0xffffffffu, wv, 2);
    const float w3 = __shfl_sync(0xffffffffu, wv, 3);
    const float w4 = __shfl_sync(0xffffffffu, wv, 4);
    const float w5 = __shfl_sync(0xffffffffu, wv, 5);
    const float w6 = __shfl_sync(0xffffffffu, wv, 6);
    const float w7 = __shfl_sync(0xffffffffu, wv, 7);

    float4 acc;
    acc.x = v0.x * w0;  acc.y = v0.y * w0;  acc.z = v0.z * w0;  acc.w = v0.w * w0;
    acc.x += v1.x * w1; acc.y += v1.y * w1; acc.z += v1.z * w1; acc.w += v1.w * w1;
    acc.x += v2.x * w2; acc.y += v2.y * w2; acc.z += v2.z * w2; acc.w += v2.w * w2;
    acc.x += v3.x * w3; acc.y += v3.y * w3; acc.z += v3.z * w3; acc.w += v3.w * w3;
    acc.x += v4.x * w4; acc.y += v4.y * w4; acc.z += v4.z * w4; acc.w += v4.w * w4;
    acc.x += v5.x * w5; acc.y += v5.y * w5; acc.z += v5.z * w5; acc.w += v5.w * w5;
    acc.x += v6.x * w6; acc.y += v6.y * w6; acc.z += v6.z * w6; acc.w += v6.w * w6;
    acc.x += v7.x * w7; acc.y += v7.y * w7; acc.z += v7.z * w7; acc.w += v7.w * w7;
    ob[t] = acc;   // default write-back store — L2-absorbed

    // A_full[m, j] = (j>>3 == m) ? tanh(blocks[j]) : 0 — b==0 CTAs, 256 float4/row.
    if (b == 0 && threadIdx.x < 256) {
        const int j0 = threadIdx.x * 4;
        float4 a = make_float4(0.f, 0.f, 0.f, 0.f);
        if ((j0 >> 3) == m) {
            if (j0 & 4) { a.x = w4; a.y = w5; a.z = w6; a.w = w7; }
            else        { a.x = w0; a.y = w1; a.z = w2; a.w = w3; }
        }
        reinterpret_cast<float4*>(afull_out + (size_t)m * NCH)[threadIdx.x] = a;
    }
}

extern "C" void kernel_launch(void* const* d_in, const int* in_sizes, int n_in,
                              void* d_out, int out_size)
{
    const float* x      = (const float*)d_in[0];
    const float* blocks = (const float*)d_in[1];
    float* out = (float*)d_out;

    // Output layout: Ax (B*M*T floats) followed by A_full (M*NCH floats)
    float* ax_out    = out;
    float* afull_out = out + (size_t)BSZ * MOUT * TLEN;

    fused_kernel<<<BSZ * MOUT, 512>>>(x, blocks, ax_out, afull_out);
}

// round 12
// speedup vs baseline: 1.0817x; 1.0217x over previous
#include <cuda_runtime.h>

// Problem constants
#define BSZ   16
#define MOUT  128
#define CBLK  8
#define NCH   1024
#define TLEN  2048
#define T4    (TLEN / 4)   // 512 float4 per row

// FINAL (converged) kernel — R6/R9 consensus structure.
//  Ax[b,m,t] = sum_c x[b, m*8+c, t] * tanh(blocks[m,c])
//  One CTA of 512 threads per (b,m) row; each thread produces one float4.
//  - All 8 x-loads issue FIRST as __ldcs (evict-first; x touched exactly once).
//  - tanh weights computed per-warp (lanes 0-7) + shuffle-broadcast under the
//    load shadow: zero barriers, zero shared memory.
//  - Ax stored with __stcs (fastest measured variant, R6: 23.136 us).
//  - CTAs with b==0 additionally write A_full row m (first 256 threads).
//  Measured: ~6.5 TB/s combined traffic — at the sm_103a LTS/HBM mixed-RW
//  ceiling; fusion and barrier-removal were the two real wins (-4.7 us total).
__global__ void __launch_bounds__(512, 4)
fused_kernel(const float* __restrict__ x,
             const float* __restrict__ blocks,
             float* __restrict__ ax_out,
             float* __restrict__ afull_out)
{
    const int bm   = blockIdx.x;          // 0 .. BSZ*MOUT-1
    const int m    = bm & (MOUT - 1);
    const int b    = bm >> 7;             // bm / MOUT
    const int lane = threadIdx.x & 31;
    const int t    = threadIdx.x;         // 0 .. 511 — one float4 per thread

    const float4* __restrict__ xb =
        reinterpret_cast<const float4*>(x + ((size_t)b * NCH + (size_t)m * CBLK) * TLEN);
    float4* __restrict__ ob =
        reinterpret_cast<float4*>(ax_out + ((size_t)b * MOUT + m) * TLEN);

    // ---- Issue all 8 streaming loads first (evict-first; touched once) ----
    float4 v0 = __ldcs(xb + 0 * T4 + t);
    float4 v1 = __ldcs(xb + 1 * T4 + t);
    float4 v2 = __ldcs(xb + 2 * T4 + t);
    float4 v3 = __ldcs(xb + 3 * T4 + t);
    float4 v4 = __ldcs(xb + 4 * T4 + t);
    float4 v5 = __ldcs(xb + 5 * T4 + t);
    float4 v6 = __ldcs(xb + 6 * T4 + t);
    float4 v7 = __ldcs(xb + 7 * T4 + t);

    // ---- Compute weights under the load shadow: lane-parallel tanh + shfl ----
    const float wv = tanhf(__ldg(blocks + m * CBLK + (lane & 7)));
    const float w0 = __shfl_sync(0xffffffffu, wv, 0);
    const float w1 = __shfl_sync(0xffffffffu, wv, 1);
    const float w2 = __shfl_sync(0xffffffffu, wv, 2);
    const float w3 = __shfl_sync(0xffffffffu, wv, 3);
    const float w4 = __shfl_sync(0xffffffffu, wv, 4);
    const float w5 = __shfl_sync(0xffffffffu, wv, 5);
    const float w6 = __shfl_sync(0xffffffffu, wv, 6);
    const float w7 = __shfl_sync(0xffffffffu, wv, 7);

    float4 acc;
    acc.x = v0.x * w0;  acc.y = v0.y * w0;  acc.z = v0.z * w0;  acc.w = v0.w * w0;
    acc.x += v1.x * w1; acc.y += v1.y * w1; acc.z += v1.z * w1; acc.w += v1.w * w1;
    acc.x += v2.x * w2; acc.y += v2.y * w2; acc.z += v2.z * w2; acc.w += v2.w * w2;
    acc.x += v3.x * w3; acc.y += v3.y * w3; acc.z += v3.z * w3; acc.w += v3.w * w3;
    acc.x += v4.x * w4; acc.y += v4.y * w4; acc.z += v4.z * w4; acc.w += v4.w * w4;
    acc.x += v5.x * w5; acc.y += v5.y * w5; acc.z += v5.z * w5; acc.w += v5.w * w5;
    acc.x += v6.x * w6; acc.y += v6.y * w6; acc.z += v6.z * w6; acc.w += v6.w * w6;
    acc.x += v7.x * w7; acc.y += v7.y * w7; acc.z += v7.z * w7; acc.w += v7.w * w7;
    __stcs(ob + t, acc);

    // A_full[m, j] = (j>>3 == m) ? tanh(blocks[j]) : 0 — b==0 CTAs, 256 float4/row.
    if (b == 0 && threadIdx.x < 256) {
        const int j0 = threadIdx.x * 4;
        float4 a = make_float4(0.f, 0.f, 0.f, 0.f);
        if ((j0 >> 3) == m) {
            if (j0 & 4) { a.x = w4; a.y = w5; a.z = w6; a.w = w7; }
            else        { a.x = w0; a.y = w1; a.z = w2; a.w = w3; }
        }
        reinterpret_cast<float4*>(afull_out + (size_t)m * NCH)[threadIdx.x] = a;
    }
}

extern "C" void kernel_launch(void* const* d_in, const int* in_sizes, int n_in,
                              void* d_out, int out_size)
{
    const float* x      = (const float*)d_in[0];
    const float* blocks = (const float*)d_in[1];
    float* out = (float*)d_out;

    // Output layout: Ax (B*M*T floats) followed by A_full (M*NCH floats)
    float* ax_out    = out;
    float* afull_out = out + (size_t)BSZ * MOUT * TLEN;

    fused_kernel<<<BSZ * MOUT, 512>>>(x, blocks, ax_out, afull_out);
}